// round 3
// baseline (speedup 1.0000x reference)
#include <cuda_runtime.h>
#include <math.h>

// Problem constants
#define EB 4
#define BB 16
#define SB 256
#define CB 17
#define NB 16
#define DB 32
#define DFFB 64
#define HB 4
#define DHB 8

// Scratch (device globals; no allocations allowed)
__device__ float g_xns[BB * SB * NB];   // new_x channels 0..15
__device__ int   g_assign[BB * SB];     // expert id per (b,s)

// ---------------------------------------------------------------------------
// Kernel 1: decomposition preprocessing. One block per (b, c) with c<16.
// Computes trend (3 moving averages), season (naive rDFT + top-4 freq mask +
// inverse), new_x = x + season + trend, stores channels 0..15 to g_xns.
// ---------------------------------------------------------------------------
__global__ void preprocess_kernel(const float* __restrict__ x)
{
    __shared__ float xr[SB];
    __shared__ float Xre[129], Xim[129], amp[129];
    __shared__ int   s_kept[128];
    __shared__ int   s_keptN;

    const int c = blockIdx.x;   // 0..15
    const int b = blockIdx.y;   // 0..15
    const int t = threadIdx.x;  // 0..255

    xr[t] = x[(b * SB + t) * CB + c];
    __syncthreads();

    // ---- trend: mean of moving averages with kernels 4, 8, 12 ----
    float tr = 0.f;
    {
        #pragma unroll
        for (int ki = 0; ki < 3; ki++) {
            const int k = (ki == 0) ? 4 : (ki == 1 ? 8 : 12);
            const int pf = (k - 1) >> 1;
            float a = 0.f;
            for (int j = 0; j < k; j++) {
                int idx = t + j - pf;
                idx = idx < 0 ? 0 : (idx > SB - 1 ? SB - 1 : idx);
                a += xr[idx];
            }
            tr += a / (float)k;
        }
        tr *= (1.f / 3.f);
    }

    // ---- naive rDFT: 129 frequencies, exact integer phase reduction ----
    const float W2PI = 6.283185307179586f / 256.f;
    if (t < 129) {
        float re = 0.f, im = 0.f;
        for (int u = 0; u < SB; u++) {
            int ph = (t * u) & 255;
            float ang = ph * W2PI;
            if (ang > 3.14159274f) ang -= 6.28318531f;
            float sn, cs;
            __sincosf(ang, &sn, &cs);
            float xv = xr[u];
            re = fmaf(xv, cs, re);
            im = fmaf(xv, -sn, im);
        }
        Xre[t] = re; Xim[t] = im;
        amp[t] = sqrtf(re * re + im * im);
    }
    __syncthreads();

    // ---- top-4 threshold among f=1..128 (f=0 excluded = -inf in reference) --
    if (t == 0) {
        float b0 = -1e30f, b1v = -1e30f, b2v = -1e30f, b3v = -1e30f;
        for (int f = 1; f <= 128; f++) {
            float a = amp[f];
            if (a > b3v) {
                if (a > b0)       { b3v = b2v; b2v = b1v; b1v = b0; b0 = a; }
                else if (a > b1v) { b3v = b2v; b2v = b1v; b1v = a; }
                else if (a > b2v) { b3v = b2v; b2v = a; }
                else              { b3v = a; }
            }
        }
        int cnt = 0;
        for (int f = 1; f <= 128; f++)
            if (amp[f] >= b3v) s_kept[cnt++] = f;
        s_keptN = cnt;
    }
    __syncthreads();

    // ---- inverse transform of masked spectrum ----
    float season = 0.f;
    const int kn = s_keptN;
    for (int ii = 0; ii < kn; ii++) {
        int f = s_kept[ii];
        if (f == 128) {
            season += Xre[128] * ((t & 1) ? -1.f : 1.f);
        } else {
            int ph = (f * t) & 255;
            float ang = ph * W2PI;
            if (ang > 3.14159274f) ang -= 6.28318531f;
            float sn, cs;
            __sincosf(ang, &sn, &cs);
            season += 2.f * (Xre[f] * cs - Xim[f] * sn);
        }
    }
    season *= (1.f / 256.f);

    g_xns[(b * SB + t) * NB + c] = xr[t] + season + tr;
}

// ---------------------------------------------------------------------------
// Kernel 2: score min/max -> bins -> expert assignment. Single block.
// ---------------------------------------------------------------------------
__global__ void assign_kernel(const float* __restrict__ orig)
{
    __shared__ float smn[256], smx[256];
    __shared__ float bins[EB + 1];
    const int t = threadIdx.x;

    float mn = 1e30f, mx = -1e30f;
    for (int i = t; i < BB * SB; i += 256) {
        float v = orig[2 * i + 1];
        mn = fminf(mn, v);
        mx = fmaxf(mx, v);
    }
    smn[t] = mn; smx[t] = mx;
    __syncthreads();
    for (int off = 128; off > 0; off >>= 1) {
        if (t < off) {
            smn[t] = fminf(smn[t], smn[t + off]);
            smx[t] = fmaxf(smx[t], smx[t + off]);
        }
        __syncthreads();
    }
    if (t == 0) {
        float lo = smn[0], hi = smx[0];
        float st = (hi - lo) * 0.25f;
        for (int j = 0; j <= EB; j++) bins[j] = lo + j * st;
    }
    __syncthreads();
    for (int i = t; i < BB * SB; i += 256) {
        float v = orig[2 * i + 1];
        int cnt = 0;
        #pragma unroll
        for (int j = 0; j <= EB; j++) cnt += (bins[j] <= v) ? 1 : 0;
        int a = cnt - 1;
        a = a < 0 ? 0 : (a > EB - 1 ? EB - 1 : a);
        g_assign[i] = a;
    }
}

// ---------------------------------------------------------------------------
// 32x32 matvec from shared-memory weight (row-major [k][j]) into reg acc[32].
// Fully unrolled so vin/acc stay register-resident; float4 broadcast LDS.
// ---------------------------------------------------------------------------
__device__ __forceinline__ void matvec32(const float* __restrict__ Wsm,
                                         const float (&vin)[32],
                                         float (&acc)[32])
{
    #pragma unroll
    for (int k2 = 0; k2 < 32; k2++) {
        const float zz = vin[k2];
        const float4* wr = reinterpret_cast<const float4*>(Wsm + k2 * 32);
        #pragma unroll
        for (int j4 = 0; j4 < 8; j4++) {
            float4 w = wr[j4];
            acc[j4 * 4 + 0] = fmaf(zz, w.x, acc[j4 * 4 + 0]);
            acc[j4 * 4 + 1] = fmaf(zz, w.y, acc[j4 * 4 + 1]);
            acc[j4 * 4 + 2] = fmaf(zz, w.z, acc[j4 * 4 + 2]);
            acc[j4 * 4 + 3] = fmaf(zz, w.w, acc[j4 * 4 + 3]);
        }
    }
}

// ---------------------------------------------------------------------------
// Kernel 3: expert transformer forward. One block per (n, b, e). 256 threads,
// one per sequence position. fp32 FFMA throughout, online softmax (no max
// subtraction; logits are O(10) for this data, clamped for safety).
// Smem: weights + K/V tiles (row stride 36 floats -> float4-aligned,
// conflict-free). 107.6 KB dynamic -> 2 blocks/SM.
// ---------------------------------------------------------------------------
#define KV_STRIDE 36
#define SMEM_FLOATS (8480 + 2 * SB * KV_STRIDE)

__global__ void __launch_bounds__(256, 2) expert_kernel(
    const float* __restrict__ startW, const float* __restrict__ startb,
    const float* __restrict__ Wq, const float* __restrict__ Wk,
    const float* __restrict__ Wv, const float* __restrict__ Wo,
    const float* __restrict__ ln1g, const float* __restrict__ ln1b,
    const float* __restrict__ ln2g, const float* __restrict__ ln2b,
    const float* __restrict__ W1, const float* __restrict__ b1,
    const float* __restrict__ W2, const float* __restrict__ b2,
    float* __restrict__ out)
{
    extern __shared__ float sm[];
    float* sWq   = sm;
    float* sWk   = sm + 1024;
    float* sWv   = sm + 2048;
    float* sWo   = sm + 3072;
    float* sW1   = sm + 4096;   // 32x64
    float* sW2   = sm + 6144;   // 64x32
    float* sln1g = sm + 8192;
    float* sln1b = sm + 8224;
    float* sln2g = sm + 8256;
    float* sln2b = sm + 8288;
    float* sb1v  = sm + 8320;   // 64
    float* sb2v  = sm + 8384;   // 32
    float* ssW   = sm + 8416;
    float* ssb   = sm + 8448;
    float* Ksm   = sm + 8480;                  // [256][36]
    float* Vsm   = sm + 8480 + SB * KV_STRIDE; // [256][36]

    const int t = threadIdx.x;
    const int n = blockIdx.x, b = blockIdx.y, e = blockIdx.z;

    // cooperative weight staging
    {
        const float* gq = Wq + e * 1024;
        const float* gk = Wk + e * 1024;
        const float* gv = Wv + e * 1024;
        const float* go = Wo + e * 1024;
        for (int i = t; i < 1024; i += 256) {
            sWq[i] = gq[i]; sWk[i] = gk[i]; sWv[i] = gv[i]; sWo[i] = go[i];
        }
        const float* g1 = W1 + e * 2048;
        const float* g2 = W2 + e * 2048;
        for (int i = t; i < 2048; i += 256) { sW1[i] = g1[i]; sW2[i] = g2[i]; }
        if (t < 32) {
            sln1g[t] = ln1g[e * 32 + t]; sln1b[t] = ln1b[e * 32 + t];
            sln2g[t] = ln2g[e * 32 + t]; sln2b[t] = ln2b[e * 32 + t];
            sb2v[t]  = b2[e * 32 + t];
            ssW[t]   = startW[t];
            ssb[t]   = startb[t];
        }
        if (t < 64) sb1v[t] = b1[e * 64 + t];
    }
    __syncthreads();

    const int s  = t;
    const int bs = b * SB + s;
    const int myassign = g_assign[bs];
    const float xval = (myassign == e) ? g_xns[bs * NB + n] : 0.f;

    // ---- h = xval*startW + startb ; z = LN1(h) ----
    float z[32];
    {
        float hv[32];
        float mean = 0.f;
        #pragma unroll
        for (int d = 0; d < 32; d++) { hv[d] = fmaf(xval, ssW[d], ssb[d]); mean += hv[d]; }
        mean *= (1.f / 32.f);
        float var = 0.f;
        #pragma unroll
        for (int d = 0; d < 32; d++) { float dd = hv[d] - mean; var = fmaf(dd, dd, var); }
        var *= (1.f / 32.f);
        float r = rsqrtf(var + 1e-5f);
        #pragma unroll
        for (int d = 0; d < 32; d++)
            z[d] = fmaf((hv[d] - mean) * r, sln1g[d], sln1b[d]);
    }

    // ---- q (regs), k/v (smem) ----
    float q[32];
    #pragma unroll
    for (int i = 0; i < 32; i++) q[i] = 0.f;
    matvec32(sWq, z, q);
    {
        float acc[32];
        #pragma unroll
        for (int i = 0; i < 32; i++) acc[i] = 0.f;
        matvec32(sWk, z, acc);
        float4* kw = reinterpret_cast<float4*>(Ksm + s * KV_STRIDE);
        #pragma unroll
        for (int j4 = 0; j4 < 8; j4++)
            kw[j4] = make_float4(acc[4*j4], acc[4*j4+1], acc[4*j4+2], acc[4*j4+3]);
    }
    {
        float acc[32];
        #pragma unroll
        for (int i = 0; i < 32; i++) acc[i] = 0.f;
        matvec32(sWv, z, acc);
        float4* vw = reinterpret_cast<float4*>(Vsm + s * KV_STRIDE);
        #pragma unroll
        for (int j4 = 0; j4 < 8; j4++)
            vw[j4] = make_float4(acc[4*j4], acc[4*j4+1], acc[4*j4+2], acc[4*j4+3]);
    }
    __syncthreads();

    // ---- attention: 4 heads of 8, online accumulation ----
    const float att_scale = 0.3535533905932738f; // 1/sqrt(8)
    float o[32];
    #pragma unroll
    for (int i = 0; i < 32; i++) o[i] = 0.f;
    float lsum[4] = {0.f, 0.f, 0.f, 0.f};

    for (int key = 0; key < SB; key++) {
        const float4* kr = reinterpret_cast<const float4*>(Ksm + key * KV_STRIDE);
        const float4* vr = reinterpret_cast<const float4*>(Vsm + key * KV_STRIDE);
        #pragma unroll
        for (int hh = 0; hh < 4; hh++) {
            float4 ka = kr[2 * hh], kb = kr[2 * hh + 1];
            float lg = q[8*hh + 0] * ka.x;
            lg = fmaf(q[8*hh + 1], ka.y, lg);
            lg = fmaf(q[8*hh + 2], ka.z, lg);
            lg = fmaf(q[8*hh + 3], ka.w, lg);
            lg = fmaf(q[8*hh + 4], kb.x, lg);
            lg = fmaf(q[8*hh + 5], kb.y, lg);
            lg = fmaf(q[8*hh + 6], kb.z, lg);
            lg = fmaf(q[8*hh + 7], kb.w, lg);
            float p = __expf(fminf(lg * att_scale, 80.f));
            lsum[hh] += p;
            float4 va = vr[2 * hh], vb = vr[2 * hh + 1];
            o[8*hh + 0] = fmaf(p, va.x, o[8*hh + 0]);
            o[8*hh + 1] = fmaf(p, va.y, o[8*hh + 1]);
            o[8*hh + 2] = fmaf(p, va.z, o[8*hh + 2]);
            o[8*hh + 3] = fmaf(p, va.w, o[8*hh + 3]);
            o[8*hh + 4] = fmaf(p, vb.x, o[8*hh + 4]);
            o[8*hh + 5] = fmaf(p, vb.y, o[8*hh + 5]);
            o[8*hh + 6] = fmaf(p, vb.z, o[8*hh + 6]);
            o[8*hh + 7] = fmaf(p, vb.w, o[8*hh + 7]);
        }
    }
    #pragma unroll
    for (int hh = 0; hh < 4; hh++) {
        float inv = 1.0f / lsum[hh];
        #pragma unroll
        for (int d = 0; d < 8; d++) o[8*hh + d] *= inv;
    }

    // ---- h2 = h + o @ Wo ----
    float h2[32];
    #pragma unroll
    for (int d = 0; d < 32; d++) h2[d] = fmaf(xval, ssW[d], ssb[d]);
    matvec32(sWo, o, h2);

    // ---- z2 = LN2(h2) ----
    float z2[32];
    {
        float mean = 0.f;
        #pragma unroll
        for (int d = 0; d < 32; d++) mean += h2[d];
        mean *= (1.f / 32.f);
        float var = 0.f;
        #pragma unroll
        for (int d = 0; d < 32; d++) { float dd = h2[d] - mean; var = fmaf(dd, dd, var); }
        var *= (1.f / 32.f);
        float r = rsqrtf(var + 1e-5f);
        #pragma unroll
        for (int d = 0; d < 32; d++)
            z2[d] = fmaf((h2[d] - mean) * r, sln2g[d], sln2b[d]);
    }

    // ---- FFN: h3 = h2 + relu(z2@W1 + b1)@W2 + b2, streamed in two halves ----
    float h3[32];
    #pragma unroll
    for (int d = 0; d < 32; d++) h3[d] = h2[d] + sb2v[d];

    #pragma unroll
    for (int half = 0; half < 2; half++) {
        float fh[32];
        #pragma unroll
        for (int j = 0; j < 32; j++) fh[j] = sb1v[half * 32 + j];
        #pragma unroll
        for (int k2 = 0; k2 < 32; k2++) {
            float zz = z2[k2];
            const float4* wr = reinterpret_cast<const float4*>(sW1 + k2 * 64 + half * 32);
            #pragma unroll
            for (int j4 = 0; j4 < 8; j4++) {
                float4 w = wr[j4];
                fh[j4*4 + 0] = fmaf(zz, w.x, fh[j4*4 + 0]);
                fh[j4*4 + 1] = fmaf(zz, w.y, fh[j4*4 + 1]);
                fh[j4*4 + 2] = fmaf(zz, w.z, fh[j4*4 + 2]);
                fh[j4*4 + 3] = fmaf(zz, w.w, fh[j4*4 + 3]);
            }
        }
        #pragma unroll
        for (int j = 0; j < 32; j++) fh[j] = fmaxf(fh[j], 0.f);
        #pragma unroll
        for (int j = 0; j < 32; j++) {
            float fj = fh[j];
            const float4* wr = reinterpret_cast<const float4*>(sW2 + (half * 32 + j) * 32);
            #pragma unroll
            for (int d4 = 0; d4 < 8; d4++) {
                float4 w = wr[d4];
                h3[d4*4 + 0] = fmaf(fj, w.x, h3[d4*4 + 0]);
                h3[d4*4 + 1] = fmaf(fj, w.y, h3[d4*4 + 1]);
                h3[d4*4 + 2] = fmaf(fj, w.z, h3[d4*4 + 2]);
                h3[d4*4 + 3] = fmaf(fj, w.w, h3[d4*4 + 3]);
            }
        }
    }

    // ---- combine: only the assigned expert writes (exactly one per (b,s)) ----
    if (myassign == e) {
        float4* op = reinterpret_cast<float4*>(out + ((bs * NB) + n) * DB);
        #pragma unroll
        for (int d4 = 0; d4 < 8; d4++)
            op[d4] = make_float4(h3[4*d4], h3[4*d4+1], h3[4*d4+2], h3[4*d4+3]);
    }
}

// ---------------------------------------------------------------------------
extern "C" void kernel_launch(void* const* d_in, const int* in_sizes, int n_in,
                              void* d_out, int out_size)
{
    const float* x      = (const float*)d_in[0];
    const float* orig   = (const float*)d_in[1];
    const float* startW = (const float*)d_in[2];
    const float* startb = (const float*)d_in[3];
    const float* Wq     = (const float*)d_in[4];
    const float* Wk     = (const float*)d_in[5];
    const float* Wv     = (const float*)d_in[6];
    const float* Wo     = (const float*)d_in[7];
    const float* l1g    = (const float*)d_in[8];
    const float* l1b    = (const float*)d_in[9];
    const float* l2g    = (const float*)d_in[10];
    const float* l2b    = (const float*)d_in[11];
    const float* W1     = (const float*)d_in[12];
    const float* b1     = (const float*)d_in[13];
    const float* W2     = (const float*)d_in[14];
    const float* b2     = (const float*)d_in[15];
    float* out = (float*)d_out;

    preprocess_kernel<<<dim3(NB, BB), 256>>>(x);
    assign_kernel<<<1, 256>>>(orig);

    const int smem_bytes = SMEM_FLOATS * (int)sizeof(float);
    cudaFuncSetAttribute(expert_kernel,
                         cudaFuncAttributeMaxDynamicSharedMemorySize, smem_bytes);
    expert_kernel<<<dim3(NB, BB, EB), 256, smem_bytes>>>(
        startW, startb, Wq, Wk, Wv, Wo,
        l1g, l1b, l2g, l2b, W1, b1, W2, b2, out);
}

// round 4
// speedup vs baseline: 2.3169x; 2.3169x over previous
#include <cuda_runtime.h>
#include <math.h>

// Problem constants
#define EB 4
#define BB 16
#define SB 256
#define CB 17
#define NB 16
#define DB 32
#define DFFB 64
#define HB 4
#define DHB 8

// Scratch (device globals; no allocations allowed)
__device__ float g_xns[BB * SB * NB];        // new_x channels 0..15
__device__ int   g_assign[BB * SB];          // expert id per (b,s)
__device__ int   g_list[EB * BB * SB];       // compacted s-indices per (e,b)
__device__ int   g_cnt[EB * BB];             // counts per (e,b)

// ---------------------------------------------------------------------------
// Kernel 1: decomposition preprocessing. One block per (b, c) with c<16.
// Sin/cos via exact-integer-phase smem tables (replaces 33K MUFU sincos).
// ---------------------------------------------------------------------------
__global__ void preprocess_kernel(const float* __restrict__ x)
{
    __shared__ float xr[SB];
    __shared__ float ctab[SB], stab[SB];
    __shared__ float Xre[129], Xim[129], amp[129];
    __shared__ int   s_kept[128];
    __shared__ int   s_keptN;

    const int c = blockIdx.x;   // 0..15
    const int b = blockIdx.y;   // 0..15
    const int t = threadIdx.x;  // 0..255

    xr[t] = x[(b * SB + t) * CB + c];
    {
        const float W2PI = 6.283185307179586f / 256.f;
        float sn, cs;
        sincosf(t * W2PI, &sn, &cs);
        ctab[t] = cs; stab[t] = sn;
    }
    __syncthreads();

    // ---- trend: mean of moving averages with kernels 4, 8, 12 ----
    float tr = 0.f;
    {
        #pragma unroll
        for (int ki = 0; ki < 3; ki++) {
            const int k = (ki == 0) ? 4 : (ki == 1 ? 8 : 12);
            const int pf = (k - 1) >> 1;
            float a = 0.f;
            for (int j = 0; j < k; j++) {
                int idx = t + j - pf;
                idx = idx < 0 ? 0 : (idx > SB - 1 ? SB - 1 : idx);
                a += xr[idx];
            }
            tr += a / (float)k;
        }
        tr *= (1.f / 3.f);
    }

    // ---- naive rDFT: 129 frequencies via table lookup ----
    if (t < 129) {
        float re = 0.f, im = 0.f;
        for (int u = 0; u < SB; u++) {
            int ph = (t * u) & 255;
            float xv = xr[u];
            re = fmaf(xv,  ctab[ph], re);
            im = fmaf(xv, -stab[ph], im);
        }
        Xre[t] = re; Xim[t] = im;
        amp[t] = sqrtf(re * re + im * im);
    }
    __syncthreads();

    // ---- top-4 threshold among f=1..128 (f=0 = -inf in reference) ----
    if (t == 0) {
        float b0 = -1e30f, b1v = -1e30f, b2v = -1e30f, b3v = -1e30f;
        for (int f = 1; f <= 128; f++) {
            float a = amp[f];
            if (a > b3v) {
                if (a > b0)       { b3v = b2v; b2v = b1v; b1v = b0; b0 = a; }
                else if (a > b1v) { b3v = b2v; b2v = b1v; b1v = a; }
                else if (a > b2v) { b3v = b2v; b2v = a; }
                else              { b3v = a; }
            }
        }
        int cnt = 0;
        for (int f = 1; f <= 128; f++)
            if (amp[f] >= b3v) s_kept[cnt++] = f;
        s_keptN = cnt;
    }
    __syncthreads();

    // ---- inverse transform of masked spectrum ----
    float season = 0.f;
    const int kn = s_keptN;
    for (int ii = 0; ii < kn; ii++) {
        int f = s_kept[ii];
        int ph = (f * t) & 255;
        if (f == 128) {
            season += Xre[128] * ctab[ph];     // cos(pi*t) = +-1
        } else {
            season += 2.f * (Xre[f] * ctab[ph] - Xim[f] * stab[ph]);
        }
    }
    season *= (1.f / 256.f);

    g_xns[(b * SB + t) * NB + c] = xr[t] + season + tr;
}

// ---------------------------------------------------------------------------
// Kernel 2: min/max -> bins -> assignment -> deterministic compacted lists.
// Single block of 256 threads.
// ---------------------------------------------------------------------------
__global__ void assign_kernel(const float* __restrict__ orig)
{
    __shared__ float smn[256], smx[256];
    __shared__ float bins[EB + 1];
    __shared__ int   sA[BB * SB];
    const int t = threadIdx.x;

    float mn = 1e30f, mx = -1e30f;
    for (int i = t; i < BB * SB; i += 256) {
        float v = orig[2 * i + 1];
        mn = fminf(mn, v);
        mx = fmaxf(mx, v);
    }
    smn[t] = mn; smx[t] = mx;
    __syncthreads();
    for (int off = 128; off > 0; off >>= 1) {
        if (t < off) {
            smn[t] = fminf(smn[t], smn[t + off]);
            smx[t] = fmaxf(smx[t], smx[t + off]);
        }
        __syncthreads();
    }
    if (t == 0) {
        float lo = smn[0], hi = smx[0];
        float st = (hi - lo) * 0.25f;
        for (int j = 0; j <= EB; j++) bins[j] = lo + j * st;
    }
    __syncthreads();
    for (int i = t; i < BB * SB; i += 256) {
        float v = orig[2 * i + 1];
        int cnt = 0;
        #pragma unroll
        for (int j = 0; j <= EB; j++) cnt += (bins[j] <= v) ? 1 : 0;
        int a = cnt - 1;
        a = a < 0 ? 0 : (a > EB - 1 ? EB - 1 : a);
        g_assign[i] = a;
        sA[i] = a;
    }
    __syncthreads();

    // deterministic per-(e,b) compaction: one thread per b, serial scan
    if (t < BB) {
        int cnt[EB] = {0, 0, 0, 0};
        const int base = t * SB;
        for (int s = 0; s < SB; s++) {
            int a = sA[base + s];
            g_list[(a * BB + t) * SB + cnt[a]] = s;
            cnt[a]++;
        }
        #pragma unroll
        for (int e = 0; e < EB; e++) g_cnt[e * BB + t] = cnt[e];
    }
}

// ---------------------------------------------------------------------------
// 32x32 matvec from shared-memory weight (row-major [k][j]) into reg acc[32].
// ---------------------------------------------------------------------------
__device__ __forceinline__ void matvec32(const float* __restrict__ Wsm,
                                         const float (&vin)[32],
                                         float (&acc)[32])
{
    #pragma unroll
    for (int k2 = 0; k2 < 32; k2++) {
        const float zz = vin[k2];
        const float4* wr = reinterpret_cast<const float4*>(Wsm + k2 * 32);
        #pragma unroll
        for (int j4 = 0; j4 < 8; j4++) {
            float4 w = wr[j4];
            acc[j4 * 4 + 0] = fmaf(zz, w.x, acc[j4 * 4 + 0]);
            acc[j4 * 4 + 1] = fmaf(zz, w.y, acc[j4 * 4 + 1]);
            acc[j4 * 4 + 2] = fmaf(zz, w.z, acc[j4 * 4 + 2]);
            acc[j4 * 4 + 3] = fmaf(zz, w.w, acc[j4 * 4 + 3]);
        }
    }
}

// ---------------------------------------------------------------------------
// Kernel 3: expert transformer forward on COMPACTED queries.
// One block per (n, b, e); thread t < cnt handles query s = list[t].
// All unassigned keys collapse to one aggregated (k_const, v_const) term:
//   lsum += (256-cnt)*exp(q.k_const*scale);  o += (256-cnt)*p_const*v_const
// which is algebraically identical to the reference softmax over 256 keys.
// ---------------------------------------------------------------------------
#define KV_STRIDE 36
#define SMEM_FLOATS (8544 + 2 * SB * KV_STRIDE)

__global__ void __launch_bounds__(256, 2) expert_kernel(
    const float* __restrict__ startW, const float* __restrict__ startb,
    const float* __restrict__ Wq, const float* __restrict__ Wk,
    const float* __restrict__ Wv, const float* __restrict__ Wo,
    const float* __restrict__ ln1g, const float* __restrict__ ln1b,
    const float* __restrict__ ln2g, const float* __restrict__ ln2b,
    const float* __restrict__ W1, const float* __restrict__ b1,
    const float* __restrict__ W2, const float* __restrict__ b2,
    float* __restrict__ out)
{
    extern __shared__ float sm[];
    float* sWq   = sm;
    float* sWk   = sm + 1024;
    float* sWv   = sm + 2048;
    float* sWo   = sm + 3072;
    float* sW1   = sm + 4096;   // 32x64
    float* sW2   = sm + 6144;   // 64x32
    float* sln1g = sm + 8192;
    float* sln1b = sm + 8224;
    float* sln2g = sm + 8256;
    float* sln2b = sm + 8288;
    float* sb1v  = sm + 8320;   // 64
    float* sb2v  = sm + 8384;   // 32
    float* ssW   = sm + 8416;
    float* ssb   = sm + 8448;
    float* sKc   = sm + 8480;   // k_const [32]
    float* sVc   = sm + 8512;   // v_const [32]
    float* Ksm   = sm + 8544;                  // [<=256][36]
    float* Vsm   = sm + 8544 + SB * KV_STRIDE; // [<=256][36]

    const int t = threadIdx.x;
    const int n = blockIdx.x, b = blockIdx.y, e = blockIdx.z;

    // cooperative weight staging
    {
        const float* gq = Wq + e * 1024;
        const float* gk = Wk + e * 1024;
        const float* gv = Wv + e * 1024;
        const float* go = Wo + e * 1024;
        for (int i = t; i < 1024; i += 256) {
            sWq[i] = gq[i]; sWk[i] = gk[i]; sWv[i] = gv[i]; sWo[i] = go[i];
        }
        const float* g1 = W1 + e * 2048;
        const float* g2 = W2 + e * 2048;
        for (int i = t; i < 2048; i += 256) { sW1[i] = g1[i]; sW2[i] = g2[i]; }
        if (t < 32) {
            sln1g[t] = ln1g[e * 32 + t]; sln1b[t] = ln1b[e * 32 + t];
            sln2g[t] = ln2g[e * 32 + t]; sln2b[t] = ln2b[e * 32 + t];
            sb2v[t]  = b2[e * 32 + t];
            ssW[t]   = startW[t];
            ssb[t]   = startb[t];
        }
        if (t < 64) sb1v[t] = b1[e * 64 + t];
    }
    __syncthreads();

    const int cnt = g_cnt[e * BB + b];

    // ---- per-expert constant key/value for all unassigned rows ----
    // h_const = start_b; z_const = LN1(h_const); k/v_const = z_const @ Wk/Wv
    if (t < 32) {
        float m = 0.f;
        #pragma unroll
        for (int d = 0; d < 32; d++) m += ssb[d];
        m *= (1.f / 32.f);
        float var = 0.f;
        #pragma unroll
        for (int d = 0; d < 32; d++) { float dd = ssb[d] - m; var = fmaf(dd, dd, var); }
        var *= (1.f / 32.f);
        float r = rsqrtf(var + 1e-5f);
        float kc = 0.f, vc = 0.f;
        #pragma unroll
        for (int k2 = 0; k2 < 32; k2++) {
            float zc = fmaf((ssb[k2] - m) * r, sln1g[k2], sln1b[k2]);
            kc = fmaf(zc, sWk[k2 * 32 + t], kc);
            vc = fmaf(zc, sWv[k2 * 32 + t], vc);
        }
        sKc[t] = kc; sVc[t] = vc;
    }

    int s = 0;
    float xval = 0.f;
    float q[32];
    if (t < cnt) {
        s = g_list[(e * BB + b) * SB + t];
        xval = g_xns[(b * SB + s) * NB + n];

        // ---- h = xval*startW + startb ; z = LN1(h) ----
        float z[32];
        {
            float hv[32];
            float mean = 0.f;
            #pragma unroll
            for (int d = 0; d < 32; d++) { hv[d] = fmaf(xval, ssW[d], ssb[d]); mean += hv[d]; }
            mean *= (1.f / 32.f);
            float var = 0.f;
            #pragma unroll
            for (int d = 0; d < 32; d++) { float dd = hv[d] - mean; var = fmaf(dd, dd, var); }
            var *= (1.f / 32.f);
            float r = rsqrtf(var + 1e-5f);
            #pragma unroll
            for (int d = 0; d < 32; d++)
                z[d] = fmaf((hv[d] - mean) * r, sln1g[d], sln1b[d]);
        }

        #pragma unroll
        for (int i = 0; i < 32; i++) q[i] = 0.f;
        matvec32(sWq, z, q);
        {
            float acc[32];
            #pragma unroll
            for (int i = 0; i < 32; i++) acc[i] = 0.f;
            matvec32(sWk, z, acc);
            float4* kw = reinterpret_cast<float4*>(Ksm + t * KV_STRIDE);
            #pragma unroll
            for (int j4 = 0; j4 < 8; j4++)
                kw[j4] = make_float4(acc[4*j4], acc[4*j4+1], acc[4*j4+2], acc[4*j4+3]);
        }
        {
            float acc[32];
            #pragma unroll
            for (int i = 0; i < 32; i++) acc[i] = 0.f;
            matvec32(sWv, z, acc);
            float4* vw = reinterpret_cast<float4*>(Vsm + t * KV_STRIDE);
            #pragma unroll
            for (int j4 = 0; j4 < 8; j4++)
                vw[j4] = make_float4(acc[4*j4], acc[4*j4+1], acc[4*j4+2], acc[4*j4+3]);
        }
    }
    __syncthreads();

    if (t < cnt) {
        // ---- attention over cnt assigned keys + aggregated const key ----
        const float att_scale = 0.3535533905932738f; // 1/sqrt(8)
        float o[32];
        #pragma unroll
        for (int i = 0; i < 32; i++) o[i] = 0.f;
        float lsum[4] = {0.f, 0.f, 0.f, 0.f};

        for (int key = 0; key < cnt; key++) {
            const float4* kr = reinterpret_cast<const float4*>(Ksm + key * KV_STRIDE);
            const float4* vr = reinterpret_cast<const float4*>(Vsm + key * KV_STRIDE);
            #pragma unroll
            for (int hh = 0; hh < 4; hh++) {
                float4 ka = kr[2 * hh], kb = kr[2 * hh + 1];
                float lg = q[8*hh + 0] * ka.x;
                lg = fmaf(q[8*hh + 1], ka.y, lg);
                lg = fmaf(q[8*hh + 2], ka.z, lg);
                lg = fmaf(q[8*hh + 3], ka.w, lg);
                lg = fmaf(q[8*hh + 4], kb.x, lg);
                lg = fmaf(q[8*hh + 5], kb.y, lg);
                lg = fmaf(q[8*hh + 6], kb.z, lg);
                lg = fmaf(q[8*hh + 7], kb.w, lg);
                float p = __expf(fminf(lg * att_scale, 80.f));
                lsum[hh] += p;
                float4 va = vr[2 * hh], vb = vr[2 * hh + 1];
                o[8*hh + 0] = fmaf(p, va.x, o[8*hh + 0]);
                o[8*hh + 1] = fmaf(p, va.y, o[8*hh + 1]);
                o[8*hh + 2] = fmaf(p, va.z, o[8*hh + 2]);
                o[8*hh + 3] = fmaf(p, va.w, o[8*hh + 3]);
                o[8*hh + 4] = fmaf(p, vb.x, o[8*hh + 4]);
                o[8*hh + 5] = fmaf(p, vb.y, o[8*hh + 5]);
                o[8*hh + 6] = fmaf(p, vb.z, o[8*hh + 6]);
                o[8*hh + 7] = fmaf(p, vb.w, o[8*hh + 7]);
            }
        }
        // aggregated constant-key term: weight (256 - cnt)
        {
            const float w = (float)(SB - cnt);
            const float4* kr = reinterpret_cast<const float4*>(sKc);
            const float4* vr = reinterpret_cast<const float4*>(sVc);
            #pragma unroll
            for (int hh = 0; hh < 4; hh++) {
                float4 ka = kr[2 * hh], kb = kr[2 * hh + 1];
                float lg = q[8*hh + 0] * ka.x;
                lg = fmaf(q[8*hh + 1], ka.y, lg);
                lg = fmaf(q[8*hh + 2], ka.z, lg);
                lg = fmaf(q[8*hh + 3], ka.w, lg);
                lg = fmaf(q[8*hh + 4], kb.x, lg);
                lg = fmaf(q[8*hh + 5], kb.y, lg);
                lg = fmaf(q[8*hh + 6], kb.z, lg);
                lg = fmaf(q[8*hh + 7], kb.w, lg);
                float p = w * __expf(fminf(lg * att_scale, 80.f));
                lsum[hh] += p;
                float4 va = vr[2 * hh], vb = vr[2 * hh + 1];
                o[8*hh + 0] = fmaf(p, va.x, o[8*hh + 0]);
                o[8*hh + 1] = fmaf(p, va.y, o[8*hh + 1]);
                o[8*hh + 2] = fmaf(p, va.z, o[8*hh + 2]);
                o[8*hh + 3] = fmaf(p, va.w, o[8*hh + 3]);
                o[8*hh + 4] = fmaf(p, vb.x, o[8*hh + 4]);
                o[8*hh + 5] = fmaf(p, vb.y, o[8*hh + 5]);
                o[8*hh + 6] = fmaf(p, vb.z, o[8*hh + 6]);
                o[8*hh + 7] = fmaf(p, vb.w, o[8*hh + 7]);
            }
        }
        #pragma unroll
        for (int hh = 0; hh < 4; hh++) {
            float inv = 1.0f / lsum[hh];
            #pragma unroll
            for (int d = 0; d < 8; d++) o[8*hh + d] *= inv;
        }

        // ---- h2 = h + o @ Wo ----
        float h2[32];
        #pragma unroll
        for (int d = 0; d < 32; d++) h2[d] = fmaf(xval, ssW[d], ssb[d]);
        matvec32(sWo, o, h2);

        // ---- z2 = LN2(h2) ----
        float z2[32];
        {
            float mean = 0.f;
            #pragma unroll
            for (int d = 0; d < 32; d++) mean += h2[d];
            mean *= (1.f / 32.f);
            float var = 0.f;
            #pragma unroll
            for (int d = 0; d < 32; d++) { float dd = h2[d] - mean; var = fmaf(dd, dd, var); }
            var *= (1.f / 32.f);
            float r = rsqrtf(var + 1e-5f);
            #pragma unroll
            for (int d = 0; d < 32; d++)
                z2[d] = fmaf((h2[d] - mean) * r, sln2g[d], sln2b[d]);
        }

        // ---- FFN ----
        float h3[32];
        #pragma unroll
        for (int d = 0; d < 32; d++) h3[d] = h2[d] + sb2v[d];

        #pragma unroll
        for (int half = 0; half < 2; half++) {
            float fh[32];
            #pragma unroll
            for (int j = 0; j < 32; j++) fh[j] = sb1v[half * 32 + j];
            #pragma unroll
            for (int k2 = 0; k2 < 32; k2++) {
                float zz = z2[k2];
                const float4* wr = reinterpret_cast<const float4*>(sW1 + k2 * 64 + half * 32);
                #pragma unroll
                for (int j4 = 0; j4 < 8; j4++) {
                    float4 w = wr[j4];
                    fh[j4*4 + 0] = fmaf(zz, w.x, fh[j4*4 + 0]);
                    fh[j4*4 + 1] = fmaf(zz, w.y, fh[j4*4 + 1]);
                    fh[j4*4 + 2] = fmaf(zz, w.z, fh[j4*4 + 2]);
                    fh[j4*4 + 3] = fmaf(zz, w.w, fh[j4*4 + 3]);
                }
            }
            #pragma unroll
            for (int j = 0; j < 32; j++) fh[j] = fmaxf(fh[j], 0.f);
            #pragma unroll
            for (int j = 0; j < 32; j++) {
                float fj = fh[j];
                const float4* wr = reinterpret_cast<const float4*>(sW2 + (half * 32 + j) * 32);
                #pragma unroll
                for (int d4 = 0; d4 < 8; d4++) {
                    float4 w = wr[d4];
                    h3[d4*4 + 0] = fmaf(fj, w.x, h3[d4*4 + 0]);
                    h3[d4*4 + 1] = fmaf(fj, w.y, h3[d4*4 + 1]);
                    h3[d4*4 + 2] = fmaf(fj, w.z, h3[d4*4 + 2]);
                    h3[d4*4 + 3] = fmaf(fj, w.w, h3[d4*4 + 3]);
                }
            }
        }

        // ---- write (each assigned (b,s) is written by exactly this block) ----
        const int bs = b * SB + s;
        float4* op = reinterpret_cast<float4*>(out + ((bs * NB) + n) * DB);
        #pragma unroll
        for (int d4 = 0; d4 < 8; d4++)
            op[d4] = make_float4(h3[4*d4], h3[4*d4+1], h3[4*d4+2], h3[4*d4+3]);
    }
}

// ---------------------------------------------------------------------------
extern "C" void kernel_launch(void* const* d_in, const int* in_sizes, int n_in,
                              void* d_out, int out_size)
{
    const float* x      = (const float*)d_in[0];
    const float* orig   = (const float*)d_in[1];
    const float* startW = (const float*)d_in[2];
    const float* startb = (const float*)d_in[3];
    const float* Wq     = (const float*)d_in[4];
    const float* Wk     = (const float*)d_in[5];
    const float* Wv     = (const float*)d_in[6];
    const float* Wo     = (const float*)d_in[7];
    const float* l1g    = (const float*)d_in[8];
    const float* l1b    = (const float*)d_in[9];
    const float* l2g    = (const float*)d_in[10];
    const float* l2b    = (const float*)d_in[11];
    const float* W1     = (const float*)d_in[12];
    const float* b1     = (const float*)d_in[13];
    const float* W2     = (const float*)d_in[14];
    const float* b2     = (const float*)d_in[15];
    float* out = (float*)d_out;

    preprocess_kernel<<<dim3(NB, BB), 256>>>(x);
    assign_kernel<<<1, 256>>>(orig);

    const int smem_bytes = SMEM_FLOATS * (int)sizeof(float);
    cudaFuncSetAttribute(expert_kernel,
                         cudaFuncAttributeMaxDynamicSharedMemorySize, smem_bytes);
    expert_kernel<<<dim3(NB, BB, EB), 256, smem_bytes>>>(
        startW, startb, Wq, Wk, Wv, Wo,
        l1g, l1b, l2g, l2b, W1, b1, W2, b2, out);
}